// round 13
// baseline (speedup 1.0000x reference)
#include <cuda_runtime.h>

// WaveletSparsityPrior: 3-level Haar DWT band-loss, single fused kernel.
// Input:  pred [64, 1, 1024, 1024] fp32 (256 MB)  ->  Output: scalar fp32
//
// Each thread owns one 8x8 input tile — the exact support of a 3-level Haar
// transform — computes every wavelet coefficient in registers, and accumulates
// sum(min(|c|, thr_j)) for the LH/HL/HH bands. Input read exactly once.
// The LAST block (fence-counter pattern) reduces the 4096 block partials from
// L2 and writes the scalar — no second kernel launch.

#define BASE_THR (50.0f / 255.0f)

// Level j=1: level_idx=3, thr=BASE/4, weight=1/3, N=64*512*512
// Level j=2: level_idx=2, thr=BASE/2, weight=1/2, N=64*256*256
// Level j=3: level_idx=1, thr=BASE,   weight=1,   N=64*128*128

#define NBLOCKS 4096
__device__ float g_part[3][NBLOCKS];     // fully written every launch
__device__ unsigned int g_count;         // 0 at load; last block resets to 0

__global__ void wavelet_kernel(const float* __restrict__ pred,
                               float* __restrict__ out) {
    const int i = blockIdx.x * 256 + threadIdx.x;   // [0, 64*128*128)
    const int b  = i >> 14;          // batch (16384 tiles per image)
    const int t  = i & 16383;
    const int ty = t >> 7;           // tile row (128 tile-rows)
    const int tx = t & 127;          // tile col (consecutive lanes -> consecutive tx)

    const float* base = pred + ((size_t)b << 20) + ((size_t)ty << 13) + (tx << 3);

    // Load 8x8 tile: 2x float4 per row; warp covers contiguous 1 KB per row.
    float a[8][8];
    #pragma unroll
    for (int r = 0; r < 8; r++) {
        float4 v0 = *reinterpret_cast<const float4*>(base + (size_t)r * 1024);
        float4 v1 = *reinterpret_cast<const float4*>(base + (size_t)r * 1024 + 4);
        a[r][0] = v0.x; a[r][1] = v0.y; a[r][2] = v0.z; a[r][3] = v0.w;
        a[r][4] = v1.x; a[r][5] = v1.y; a[r][6] = v1.z; a[r][7] = v1.w;
    }

    const float thr1 = BASE_THR * 0.25f;
    const float thr2 = BASE_THR * 0.5f;
    const float thr3 = BASE_THR;

    float s1 = 0.0f, s2 = 0.0f, s3 = 0.0f;

    // Level 1: 8x8 -> 4x4  (two INV_SQRT2 factors fold into 0.5)
    float ll1[4][4];
    #pragma unroll
    for (int r = 0; r < 4; r++) {
        #pragma unroll
        for (int c = 0; c < 4; c++) {
            float x00 = a[2*r][2*c],   x01 = a[2*r][2*c+1];
            float x10 = a[2*r+1][2*c], x11 = a[2*r+1][2*c+1];
            float lo0 = x00 + x10, lo1 = x01 + x11;
            float hi0 = x10 - x00, hi1 = x11 - x01;
            ll1[r][c] = (lo0 + lo1) * 0.5f;
            float lh = (lo1 - lo0) * 0.5f;
            float hl = (hi0 + hi1) * 0.5f;
            float hh = (hi1 - hi0) * 0.5f;
            s1 += fminf(fabsf(lh), thr1) + fminf(fabsf(hl), thr1) + fminf(fabsf(hh), thr1);
        }
    }

    // Level 2: 4x4 -> 2x2
    float ll2[2][2];
    #pragma unroll
    for (int r = 0; r < 2; r++) {
        #pragma unroll
        for (int c = 0; c < 2; c++) {
            float x00 = ll1[2*r][2*c],   x01 = ll1[2*r][2*c+1];
            float x10 = ll1[2*r+1][2*c], x11 = ll1[2*r+1][2*c+1];
            float lo0 = x00 + x10, lo1 = x01 + x11;
            float hi0 = x10 - x00, hi1 = x11 - x01;
            ll2[r][c] = (lo0 + lo1) * 0.5f;
            float lh = (lo1 - lo0) * 0.5f;
            float hl = (hi0 + hi1) * 0.5f;
            float hh = (hi1 - hi0) * 0.5f;
            s2 += fminf(fabsf(lh), thr2) + fminf(fabsf(hl), thr2) + fminf(fabsf(hh), thr2);
        }
    }

    // Level 3: 2x2 -> 1
    {
        float x00 = ll2[0][0], x01 = ll2[0][1];
        float x10 = ll2[1][0], x11 = ll2[1][1];
        float lo0 = x00 + x10, lo1 = x01 + x11;
        float hi0 = x10 - x00, hi1 = x11 - x01;
        float lh = (lo1 - lo0) * 0.5f;
        float hl = (hi0 + hi1) * 0.5f;
        float hh = (hi1 - hi0) * 0.5f;
        s3 += fminf(fabsf(lh), thr3) + fminf(fabsf(hl), thr3) + fminf(fabsf(hh), thr3);
    }

    // Warp reduction (3 accumulators)
    #pragma unroll
    for (int off = 16; off > 0; off >>= 1) {
        s1 += __shfl_xor_sync(0xFFFFFFFFu, s1, off);
        s2 += __shfl_xor_sync(0xFFFFFFFFu, s2, off);
        s3 += __shfl_xor_sync(0xFFFFFFFFu, s3, off);
    }

    __shared__ float sh1[8], sh2[8], sh3[8];
    __shared__ bool is_last;
    const int lane = threadIdx.x & 31;
    const int warp = threadIdx.x >> 5;
    if (lane == 0) { sh1[warp] = s1; sh2[warp] = s2; sh3[warp] = s3; }
    __syncthreads();

    if (warp == 0) {
        float t1 = (lane < 8) ? sh1[lane] : 0.0f;
        float t2 = (lane < 8) ? sh2[lane] : 0.0f;
        float t3 = (lane < 8) ? sh3[lane] : 0.0f;
        #pragma unroll
        for (int off = 4; off > 0; off >>= 1) {
            t1 += __shfl_xor_sync(0xFFFFFFFFu, t1, off);
            t2 += __shfl_xor_sync(0xFFFFFFFFu, t2, off);
            t3 += __shfl_xor_sync(0xFFFFFFFFu, t3, off);
        }
        if (lane == 0) {
            g_part[0][blockIdx.x] = t1;
            g_part[1][blockIdx.x] = t2;
            g_part[2][blockIdx.x] = t3;
            __threadfence();                      // order partials before counter
            unsigned int n = atomicAdd(&g_count, 1u);
            is_last = (n == NBLOCKS - 1);
        }
    }
    __syncthreads();

    // ---- Last block reduces all partials (L2-hot) and writes the scalar ----
    if (is_last) {
        const int tid = threadIdx.x;
        // 48 independent LDG.cg per thread, fully unrolled -> deep MLP, one
        // L2 round-trip for the whole 48 KB partials array.
        float p1 = 0.0f, p2 = 0.0f, p3 = 0.0f;
        #pragma unroll
        for (int k = 0; k < NBLOCKS / 256; k++) {     // 16 per band per thread
            int idx = tid + k * 256;
            p1 += __ldcg(&g_part[0][idx]);
            p2 += __ldcg(&g_part[1][idx]);
            p3 += __ldcg(&g_part[2][idx]);
        }
        #pragma unroll
        for (int off = 16; off > 0; off >>= 1) {
            p1 += __shfl_xor_sync(0xFFFFFFFFu, p1, off);
            p2 += __shfl_xor_sync(0xFFFFFFFFu, p2, off);
            p3 += __shfl_xor_sync(0xFFFFFFFFu, p3, off);
        }
        __shared__ double dh[3][8];
        if (lane == 0) {
            dh[0][warp] = (double)p1;
            dh[1][warp] = (double)p2;
            dh[2][warp] = (double)p3;
        }
        __syncthreads();
        if (tid == 0) {
            double q1 = 0.0, q2 = 0.0, q3 = 0.0;
            #pragma unroll
            for (int w = 0; w < 8; w++) { q1 += dh[0][w]; q2 += dh[1][w]; q3 += dh[2][w]; }
            // total = sum_j weight_j * band_sum_j / (3 * N_j)
            double v = (1.0 / 3.0) * q1 / (3.0 * 16777216.0)   // j=1: N=64*512^2
                     + 0.5         * q2 / (3.0 * 4194304.0)    // j=2: N=64*256^2
                     + 1.0         * q3 / (3.0 * 1048576.0);   // j=3: N=64*128^2
            out[0] = (float)v;
            g_count = 0;                          // reset for next graph replay
        }
    }
}

extern "C" void kernel_launch(void* const* d_in, const int* in_sizes, int n_in,
                              void* d_out, int out_size) {
    const float* pred = (const float*)d_in[0];
    float* out = (float*)d_out;

    // 64 images * 128*128 tiles = 1,048,576 threads = 4096 blocks of 256
    wavelet_kernel<<<NBLOCKS, 256>>>(pred, out);
}

// round 15
// speedup vs baseline: 1.0368x; 1.0368x over previous
#include <cuda_runtime.h>

// WaveletSparsityPrior: 3-level Haar DWT band-loss, single fused kernel.
// Input:  pred [64, 1, 1024, 1024] fp32 (256 MB)  ->  Output: scalar fp32
//
// Each thread owns one 8x8 input tile — the exact support of a 3-level Haar
// transform — computes every wavelet coefficient in registers, and accumulates
// sum(min(|c|, thr_j)) for the LH/HL/HH bands. Input read exactly once.
// The LAST block (fence-counter pattern) reduces the 4096 block partials from
// L2 and writes the scalar — no second kernel launch.
//
// __launch_bounds__(256, 2) is load-bearing: it raises the ptxas register
// budget to ~128/thread so all 16 LDG.128s can be front-batched (64 dst regs)
// -> MLP_eff ~16 -> DRAM latency hidden. Without it ptxas picks 36 regs and
// the kernel becomes latency-bound (measured: 48.3us @ 71% DRAM vs 41.7us).

#define BASE_THR (50.0f / 255.0f)

// Level j=1: level_idx=3, thr=BASE/4, weight=1/3, N=64*512*512
// Level j=2: level_idx=2, thr=BASE/2, weight=1/2, N=64*256*256
// Level j=3: level_idx=1, thr=BASE,   weight=1,   N=64*128*128

#define NBLOCKS 4096
__device__ float g_part[3][NBLOCKS];     // fully written every launch
__device__ unsigned int g_count;         // 0 at load; last block resets to 0

__global__ __launch_bounds__(256, 2)
void wavelet_kernel(const float* __restrict__ pred,
                    float* __restrict__ out) {
    const int i = blockIdx.x * 256 + threadIdx.x;   // [0, 64*128*128)
    const int b  = i >> 14;          // batch (16384 tiles per image)
    const int t  = i & 16383;
    const int ty = t >> 7;           // tile row (128 tile-rows)
    const int tx = t & 127;          // tile col (consecutive lanes -> consecutive tx)

    const float* base = pred + ((size_t)b << 20) + ((size_t)ty << 13) + (tx << 3);

    // Load 8x8 tile: 2x float4 per row, all 16 loads front-batched.
    float a[8][8];
    #pragma unroll
    for (int r = 0; r < 8; r++) {
        float4 v0 = *reinterpret_cast<const float4*>(base + (size_t)r * 1024);
        float4 v1 = *reinterpret_cast<const float4*>(base + (size_t)r * 1024 + 4);
        a[r][0] = v0.x; a[r][1] = v0.y; a[r][2] = v0.z; a[r][3] = v0.w;
        a[r][4] = v1.x; a[r][5] = v1.y; a[r][6] = v1.z; a[r][7] = v1.w;
    }

    const float thr1 = BASE_THR * 0.25f;
    const float thr2 = BASE_THR * 0.5f;
    const float thr3 = BASE_THR;

    float s1 = 0.0f, s2 = 0.0f, s3 = 0.0f;

    // Level 1: 8x8 -> 4x4  (two INV_SQRT2 factors fold into 0.5)
    float ll1[4][4];
    #pragma unroll
    for (int r = 0; r < 4; r++) {
        #pragma unroll
        for (int c = 0; c < 4; c++) {
            float x00 = a[2*r][2*c],   x01 = a[2*r][2*c+1];
            float x10 = a[2*r+1][2*c], x11 = a[2*r+1][2*c+1];
            float lo0 = x00 + x10, lo1 = x01 + x11;
            float hi0 = x10 - x00, hi1 = x11 - x01;
            ll1[r][c] = (lo0 + lo1) * 0.5f;
            float lh = (lo1 - lo0) * 0.5f;
            float hl = (hi0 + hi1) * 0.5f;
            float hh = (hi1 - hi0) * 0.5f;
            s1 += fminf(fabsf(lh), thr1) + fminf(fabsf(hl), thr1) + fminf(fabsf(hh), thr1);
        }
    }

    // Level 2: 4x4 -> 2x2
    float ll2[2][2];
    #pragma unroll
    for (int r = 0; r < 2; r++) {
        #pragma unroll
        for (int c = 0; c < 2; c++) {
            float x00 = ll1[2*r][2*c],   x01 = ll1[2*r][2*c+1];
            float x10 = ll1[2*r+1][2*c], x11 = ll1[2*r+1][2*c+1];
            float lo0 = x00 + x10, lo1 = x01 + x11;
            float hi0 = x10 - x00, hi1 = x11 - x01;
            ll2[r][c] = (lo0 + lo1) * 0.5f;
            float lh = (lo1 - lo0) * 0.5f;
            float hl = (hi0 + hi1) * 0.5f;
            float hh = (hi1 - hi0) * 0.5f;
            s2 += fminf(fabsf(lh), thr2) + fminf(fabsf(hl), thr2) + fminf(fabsf(hh), thr2);
        }
    }

    // Level 3: 2x2 -> 1
    {
        float x00 = ll2[0][0], x01 = ll2[0][1];
        float x10 = ll2[1][0], x11 = ll2[1][1];
        float lo0 = x00 + x10, lo1 = x01 + x11;
        float hi0 = x10 - x00, hi1 = x11 - x01;
        float lh = (lo1 - lo0) * 0.5f;
        float hl = (hi0 + hi1) * 0.5f;
        float hh = (hi1 - hi0) * 0.5f;
        s3 += fminf(fabsf(lh), thr3) + fminf(fabsf(hl), thr3) + fminf(fabsf(hh), thr3);
    }

    // Warp reduction (3 accumulators)
    #pragma unroll
    for (int off = 16; off > 0; off >>= 1) {
        s1 += __shfl_xor_sync(0xFFFFFFFFu, s1, off);
        s2 += __shfl_xor_sync(0xFFFFFFFFu, s2, off);
        s3 += __shfl_xor_sync(0xFFFFFFFFu, s3, off);
    }

    __shared__ float sh1[8], sh2[8], sh3[8];
    __shared__ bool is_last;
    const int lane = threadIdx.x & 31;
    const int warp = threadIdx.x >> 5;
    if (lane == 0) { sh1[warp] = s1; sh2[warp] = s2; sh3[warp] = s3; }
    __syncthreads();

    if (warp == 0) {
        float t1 = (lane < 8) ? sh1[lane] : 0.0f;
        float t2 = (lane < 8) ? sh2[lane] : 0.0f;
        float t3 = (lane < 8) ? sh3[lane] : 0.0f;
        #pragma unroll
        for (int off = 4; off > 0; off >>= 1) {
            t1 += __shfl_xor_sync(0xFFFFFFFFu, t1, off);
            t2 += __shfl_xor_sync(0xFFFFFFFFu, t2, off);
            t3 += __shfl_xor_sync(0xFFFFFFFFu, t3, off);
        }
        if (lane == 0) {
            g_part[0][blockIdx.x] = t1;
            g_part[1][blockIdx.x] = t2;
            g_part[2][blockIdx.x] = t3;
            __threadfence();                      // order partials before counter
            unsigned int n = atomicAdd(&g_count, 1u);
            is_last = (n == NBLOCKS - 1);
        }
    }
    __syncthreads();

    // ---- Last block reduces all partials (L2-hot) and writes the scalar ----
    if (is_last) {
        const int tid = threadIdx.x;
        // 48 independent LDG.cg per thread, fully unrolled -> deep MLP, one
        // L2 round-trip for the whole 48 KB partials array.
        float p1 = 0.0f, p2 = 0.0f, p3 = 0.0f;
        #pragma unroll
        for (int k = 0; k < NBLOCKS / 256; k++) {     // 16 per band per thread
            int idx = tid + k * 256;
            p1 += __ldcg(&g_part[0][idx]);
            p2 += __ldcg(&g_part[1][idx]);
            p3 += __ldcg(&g_part[2][idx]);
        }
        #pragma unroll
        for (int off = 16; off > 0; off >>= 1) {
            p1 += __shfl_xor_sync(0xFFFFFFFFu, p1, off);
            p2 += __shfl_xor_sync(0xFFFFFFFFu, p2, off);
            p3 += __shfl_xor_sync(0xFFFFFFFFu, p3, off);
        }
        __shared__ double dh[3][8];
        if (lane == 0) {
            dh[0][warp] = (double)p1;
            dh[1][warp] = (double)p2;
            dh[2][warp] = (double)p3;
        }
        __syncthreads();
        if (tid == 0) {
            double q1 = 0.0, q2 = 0.0, q3 = 0.0;
            #pragma unroll
            for (int w = 0; w < 8; w++) { q1 += dh[0][w]; q2 += dh[1][w]; q3 += dh[2][w]; }
            // total = sum_j weight_j * band_sum_j / (3 * N_j)
            double v = (1.0 / 3.0) * q1 / (3.0 * 16777216.0)   // j=1: N=64*512^2
                     + 0.5         * q2 / (3.0 * 4194304.0)    // j=2: N=64*256^2
                     + 1.0         * q3 / (3.0 * 1048576.0);   // j=3: N=64*128^2
            out[0] = (float)v;
            g_count = 0;                          // reset for next graph replay
        }
    }
}

extern "C" void kernel_launch(void* const* d_in, const int* in_sizes, int n_in,
                              void* d_out, int out_size) {
    const float* pred = (const float*)d_in[0];
    float* out = (float*)d_out;

    // 64 images * 128*128 tiles = 1,048,576 threads = 4096 blocks of 256
    wavelet_kernel<<<NBLOCKS, 256>>>(pred, out);
}